// round 5
// baseline (speedup 1.0000x reference)
#include <cuda_runtime.h>
#include <math.h>
#include <stdint.h>

// Graph-LSTM, legacy mma.sync.tf32 path (sm_100 non-'a' target: no tcgen05).
// All GEMM operands pre-converted to tf32 bit patterns; cp.async 3-stage pipeline.
#define NDIM 1024
#define NH   (NDIM * NDIM)
#define LSTEPS 64

#define BM 128
#define BN 128
#define BK 16
#define KITERS (NDIM / BK)      // 64
#define STAGES 3
#define AW  20                  // A smem row stride (words)
#define BW  136                 // B smem row stride (words)
#define A_WORDS (BM * AW)       // 2560
#define B_WORDS (BK * BW)       // 2176
#define STAGE_WORDS (A_WORDS + B_WORDS)   // 4736
#define SMEM_BYTES (STAGES * STAGE_WORDS * 4)  // 56832

// Scratch: xtf(64) Wigtf(2) Wfotf(2) htf(1) ahtf(1) pig(2) pfo(2) igtf(1) conv(1) c(1) f(1) o(1)
__device__ float g_scratch[79 * NH];

__device__ __forceinline__ uint32_t f2tf(float f) {
    uint32_t r;
    asm("cvt.rna.tf32.f32 %0, %1;" : "=r"(r) : "f"(f));
    return r;
}
__device__ __forceinline__ uint32_t smem_u32(const void* p) {
    uint32_t a;
    asm("{ .reg .u64 t; cvta.to.shared.u64 t, %1; cvt.u32.u64 %0, t; }" : "=r"(a) : "l"(p));
    return a;
}
__device__ __forceinline__ void cp16(uint32_t dst, const void* src) {
    asm volatile("cp.async.cg.shared.global [%0], [%1], 16;" :: "r"(dst), "l"(src));
}
#define CP_COMMIT() asm volatile("cp.async.commit_group;" ::: "memory")
#define CP_WAIT1()  asm volatile("cp.async.wait_group 1;" ::: "memory")

__device__ __forceinline__ void mma_tf32(float* c, const uint32_t* a, const uint32_t* b) {
    asm volatile(
        "mma.sync.aligned.m16n8k8.row.col.f32.tf32.tf32.f32 "
        "{%0,%1,%2,%3}, {%4,%5,%6,%7}, {%8,%9}, {%0,%1,%2,%3};"
        : "+f"(c[0]), "+f"(c[1]), "+f"(c[2]), "+f"(c[3])
        : "r"(a[0]), "r"(a[1]), "r"(a[2]), "r"(a[3]),
          "r"(b[0]), "r"(b[1]));
}

// ---------------------------------------------------------------------------
// TF32 GEMM: C[M=1024, Ntot] = A @ B. A [1024,1024] tf32-bits row-major,
// B [1024, Ntot] tf32-bits row-major. Two fused tasks per launch.
// CTA tile 128x128, BK=16, 256 thr, warp tile 64x32, cp.async 3-stage.
// ---------------------------------------------------------------------------
struct GemmTask { const float* A; const float* B; float* C; int nshift; int ldb; int ldc; int cvt; };
struct GemmParams { GemmTask t0, t1; int tiles0; };

__global__ __launch_bounds__(256, 2) void tf32_gemm(GemmParams P)
{
    extern __shared__ char smem[];
    uint32_t* smw = (uint32_t*)smem;
    const uint32_t sb = smem_u32(smem);

    const int tid  = threadIdx.x;
    const int lane = tid & 31;
    const int wid  = tid >> 5;
    const int wm   = (wid & 1) * 64;    // warp row offset (2 warps in M)
    const int wn   = (wid >> 1) * 32;   // warp col offset (4 warps in N)
    const int g    = lane >> 2;
    const int kq   = lane & 3;

    GemmTask t;
    int local = blockIdx.x;
    if (local < P.tiles0) { t = P.t0; }
    else                  { t = P.t1; local -= P.tiles0; }
    const int nt = local & ((1 << t.nshift) - 1);
    const int mt = local >> t.nshift;

    const float* Ag = t.A + (size_t)(mt * BM) * NDIM;
    const float* Bg = t.B + nt * BN;

    // cp.async mappings
    const int ar   = tid >> 1;          // A row 0..127
    const int akf  = (tid & 1) * 8;     // A k offset {0,8}
    const int bkr  = tid >> 4;          // B k row 0..15
    const int bnf  = (tid & 15) * 8;    // B n offset {0..120}

    const float* Asrc = Ag + (size_t)ar * NDIM + akf;
    const float* Bsrc = Bg + (size_t)bkr * t.ldb + bnf;

    float acc[4][4][4];
    #pragma unroll
    for (int i = 0; i < 4; i++)
        #pragma unroll
        for (int j = 0; j < 4; j++)
            #pragma unroll
            for (int k = 0; k < 4; k++) acc[i][j][k] = 0.0f;

    // stage issue
    auto issue = [&](int s, int kc) {
        const int k0 = kc * BK;
        const uint32_t abase = sb + (s * STAGE_WORDS) * 4;
        const uint32_t bbase = sb + (s * STAGE_WORDS + A_WORDS) * 4;
        cp16(abase + (ar * AW + akf) * 4,     Asrc + k0);
        cp16(abase + (ar * AW + akf + 4) * 4, Asrc + k0 + 4);
        cp16(bbase + (bkr * BW + bnf) * 4,     Bsrc + (size_t)k0 * t.ldb);
        cp16(bbase + (bkr * BW + bnf + 4) * 4, Bsrc + (size_t)k0 * t.ldb + 4);
    };

    issue(0, 0); CP_COMMIT();
    issue(1, 1); CP_COMMIT();

    for (int kc = 0; kc < KITERS; kc++) {
        const int s = kc % STAGES;
        CP_WAIT1();
        __syncthreads();
        if (kc + 2 < KITERS) issue((kc + 2) % STAGES, kc + 2);
        CP_COMMIT();

        const uint32_t* As = smw + s * STAGE_WORDS;
        const uint32_t* Bs = smw + s * STAGE_WORDS + A_WORDS;

        #pragma unroll
        for (int ks = 0; ks < BK; ks += 8) {
            uint32_t af[4][4];
            uint32_t bf[4][2];
            #pragma unroll
            for (int im = 0; im < 4; im++) {
                const int rb = wm + im * 16 + g;
                af[im][0] = As[rb * AW + ks + kq];
                af[im][1] = As[(rb + 8) * AW + ks + kq];
                af[im][2] = As[rb * AW + ks + kq + 4];
                af[im][3] = As[(rb + 8) * AW + ks + kq + 4];
            }
            #pragma unroll
            for (int in = 0; in < 4; in++) {
                const int col = wn + in * 8 + g;
                bf[in][0] = Bs[(ks + kq) * BW + col];
                bf[in][1] = Bs[(ks + kq + 4) * BW + col];
            }
            #pragma unroll
            for (int im = 0; im < 4; im++)
                #pragma unroll
                for (int in = 0; in < 4; in++)
                    mma_tf32(acc[im][in], af[im], bf[in]);
        }
        __syncthreads();
    }

    // writeback (optionally converting to tf32 bits for downstream GEMM use)
    float* Cg = t.C + (size_t)(mt * BM) * t.ldc + nt * BN;
    #pragma unroll
    for (int im = 0; im < 4; im++) {
        #pragma unroll
        for (int in = 0; in < 4; in++) {
            const int row = wm + im * 16 + g;
            const int col = wn + in * 8 + kq * 2;
            float v0 = acc[im][in][0], v1 = acc[im][in][1];
            float v2 = acc[im][in][2], v3 = acc[im][in][3];
            if (t.cvt) {
                v0 = __uint_as_float(f2tf(v0)); v1 = __uint_as_float(f2tf(v1));
                v2 = __uint_as_float(f2tf(v2)); v3 = __uint_as_float(f2tf(v3));
            }
            *(float2*)(Cg + (size_t)row * t.ldc + col)       = make_float2(v0, v1);
            *(float2*)(Cg + (size_t)(row + 8) * t.ldc + col) = make_float2(v2, v3);
        }
    }
}

// ---------------------------------------------------------------------------
// Elementwise kernels
// ---------------------------------------------------------------------------
__device__ __forceinline__ float sigmoidf_(float x) { return 1.0f / (1.0f + expf(-x)); }

__global__ void convx_kernel(const float* __restrict__ x, float* __restrict__ xtf) {
    size_t idx = (size_t)blockIdx.x * 256 + threadIdx.x;
    xtf[idx] = __uint_as_float(f2tf(x[idx]));
}

// Wigtf[k][0:1024]=tf(Whi[k]), [1024:2048]=tf(Whg[k]); same for Wfotf.
__global__ void pack_kernel(
    const float* __restrict__ Whi, const float* __restrict__ Whg,
    const float* __restrict__ Whf, const float* __restrict__ Who,
    float* __restrict__ Wigtf, float* __restrict__ Wfotf)
{
    size_t idx = (size_t)blockIdx.x * 256 + threadIdx.x;  // over 1024*2048
    int r = (int)(idx >> 11), c = (int)(idx & 2047);
    size_t srci = (size_t)r * 1024 + (c & 1023);
    Wigtf[idx] = __uint_as_float(f2tf(c < 1024 ? Whi[srci] : Whg[srci]));
    Wfotf[idx] = __uint_as_float(f2tf(c < 1024 ? Whf[srci] : Who[srci]));
}

__global__ void init_kernel(float* __restrict__ out, float* __restrict__ c,
                            float* __restrict__ htf) {
    int idx = blockIdx.x * 256 + threadIdx.x;
    out[idx] = 0.0f; c[idx] = 0.0f; htf[idx] = 0.0f;
}

// gates: igtf = tf(sig(pi+bi)*tanh(pg+bg)); f, o in fp32.
__global__ void gates_kernel(
    const float* __restrict__ bi, const float* __restrict__ bf,
    const float* __restrict__ bg, const float* __restrict__ bo,
    const float* __restrict__ pig, const float* __restrict__ pfo,
    float* __restrict__ igtf, float* __restrict__ fv, float* __restrict__ ov)
{
    int idx = blockIdx.x * 256 + threadIdx.x;
    int r = idx >> 10, c = idx & 1023;
    size_t o2 = (size_t)r * 2048 + c;
    float iv = sigmoidf_(pig[o2] + bi[c]);
    float gv = tanhf(pig[o2 + 1024] + bg[c]);
    igtf[idx] = __uint_as_float(f2tf(iv * gv));
    fv[idx] = sigmoidf_(pfo[o2] + bf[c]);
    ov[idx] = sigmoidf_(pfo[o2 + 1024] + bo[c]);
}

// cell: c = f*c + conv; h = o*tanh(c) -> hnext (fp32 out) + htf (tf32 copy)
__global__ void cell_kernel(
    const float* __restrict__ f, const float* __restrict__ o,
    const float* __restrict__ conv, float* __restrict__ c,
    float* __restrict__ hnext, float* __restrict__ htf)
{
    int idx = blockIdx.x * 256 + threadIdx.x;
    float cv = f[idx] * c[idx] + conv[idx];
    c[idx] = cv;
    float hv = o[idx] * tanhf(cv);
    hnext[idx] = hv;
    htf[idx] = __uint_as_float(f2tf(hv));
}

__global__ void tail_kernel(float* __restrict__ out, const float* __restrict__ c) {
    int idx = blockIdx.x * 256 + threadIdx.x;
    out[65 * (size_t)NH + idx] = out[64 * (size_t)NH + idx];
    out[66 * (size_t)NH + idx] = c[idx];
}

// ---------------------------------------------------------------------------
// Launcher
// ---------------------------------------------------------------------------
extern "C" void kernel_launch(void* const* d_in, const int* in_sizes, int n_in,
                              void* d_out, int out_size)
{
    const float* x   = (const float*)d_in[0];
    const float* Whi = (const float*)d_in[1];
    const float* bi  = (const float*)d_in[2];
    const float* Whf = (const float*)d_in[3];
    const float* bf  = (const float*)d_in[4];
    const float* Whg = (const float*)d_in[5];
    const float* bg  = (const float*)d_in[6];
    const float* Who = (const float*)d_in[7];
    const float* bo  = (const float*)d_in[8];
    float* out = (float*)d_out;

    static float* s = nullptr;
    static bool attr_set = false;
    if (!s) cudaGetSymbolAddress((void**)&s, g_scratch);
    if (!attr_set) {
        cudaFuncSetAttribute(tf32_gemm, cudaFuncAttributeMaxDynamicSharedMemorySize, SMEM_BYTES);
        attr_set = true;
    }

    float* xtf   = s;                     // 64 NH
    float* Wigtf = s + 64 * (size_t)NH;   // [1024,2048]
    float* Wfotf = s + 66 * (size_t)NH;   // [1024,2048]
    float* htf   = s + 68 * (size_t)NH;
    float* ahtf  = s + 69 * (size_t)NH;
    float* pig   = s + 70 * (size_t)NH;   // [1024,2048]
    float* pfo   = s + 72 * (size_t)NH;   // [1024,2048]
    float* igtf  = s + 74 * (size_t)NH;
    float* conv  = s + 75 * (size_t)NH;
    float* cbuf  = s + 76 * (size_t)NH;
    float* fbuf  = s + 77 * (size_t)NH;
    float* obuf  = s + 78 * (size_t)NH;

    const int ew_grid = NH / 256;

    convx_kernel<<<LSTEPS * (NH / 256), 256>>>(x, xtf);
    pack_kernel<<<2 * (NH / 256), 256>>>(Whi, Whg, Whf, Who, Wigtf, Wfotf);
    init_kernel<<<ew_grid, 256>>>(out, cbuf, htf);

    for (int t = 0; t < LSTEPS; t++) {
        const float* xt = xtf + (size_t)t * NH;
        float* hnext    = out + (size_t)(t + 1) * NH;

        // L1 fused: ahtf = xt @ htf (cvt out), pig = htf @ Wigtf
        GemmParams p1;
        p1.t0 = { xt,  htf,   ahtf, 3, 1024, 1024, 1 };
        p1.t1 = { htf, Wigtf, pig,  4, 2048, 2048, 0 };
        p1.tiles0 = 64;
        tf32_gemm<<<64 + 128, 256, SMEM_BYTES>>>(p1);

        // L2: pfo = ahtf @ Wfotf
        GemmParams p2;
        p2.t0 = { ahtf, Wfotf, pfo, 4, 2048, 2048, 0 };
        p2.t1 = p2.t0;
        p2.tiles0 = 128;
        tf32_gemm<<<128, 256, SMEM_BYTES>>>(p2);

        // L3: gates
        gates_kernel<<<ew_grid, 256>>>(bi, bf, bg, bo, pig, pfo, igtf, fbuf, obuf);

        // L4: conv = xt @ igtf
        GemmParams p4;
        p4.t0 = { xt, igtf, conv, 3, 1024, 1024, 0 };
        p4.t1 = p4.t0;
        p4.tiles0 = 64;
        tf32_gemm<<<64, 256, SMEM_BYTES>>>(p4);

        // L5: cell
        cell_kernel<<<ew_grid, 256>>>(fbuf, obuf, conv, cbuf, hnext, htf);
    }

    if (out_size >= 67 * NH) {
        tail_kernel<<<ew_grid, 256>>>(out, cbuf);
    }
}